// round 13
// baseline (speedup 1.0000x reference)
#include <cuda_runtime.h>
#include <cuda_fp16.h>
#include <math.h>

#define NMAX    100000
#define EMAX    1600000
#define NTYPES  17
#define DIM     128
#define GMAX    64
#define NBMAX   128
#define HTB     9      // htab helper blocks inside k_hist

// ---------------- static scratch (all zero-init; self-restoring across replays) ----------------
__device__ int   g_cnt[NMAX];      // hist fills; scatter drains back to 0
__device__ int   g_rowptr[NMAX];   // local-exclusive; + g_bsums[i>>10] on use
__device__ int   g_bsums[NBMAX];
__device__ int   g_sctr;           // scan election counter (self-resets)
__device__ unsigned g_ndp[NMAX];   // (dinv bits & ~31) | type
__device__ int2  g_edge[EMAX];     // {src, (dinv_src bits & ~31) | type_src}
__device__ float g_htab[NTYPES * DIM];
__device__ uint2 g_y1h[(size_t)NMAX * 32];   // fp16x4/lane: y1s = dinv*relu(conv1)
__device__ float g_pool[GMAX * DIM];         // k_final re-zeros
__device__ int   g_gcnt[GMAX];               // k_final re-zeros

// ---------------- kernels ----------------

// blocks 0..HTB-1: htab = emb @ W1 ; rest: in-degree histogram (4 edges/thread)
__global__ void __launch_bounds__(256) k_hist(const int* __restrict__ ei, int E,
                                              const float* __restrict__ emb,
                                              const float* __restrict__ W1) {
    int b = blockIdx.x;
    if (b < HTB) {
        int idx = b * 256 + threadIdx.x;
        if (idx < NTYPES * DIM) {
            int t = idx / DIM, o = idx % DIM;
            float a0 = 0.f, a1 = 0.f, a2 = 0.f, a3 = 0.f;
            #pragma unroll
            for (int d = 0; d < DIM; d += 4) {
                a0 = fmaf(emb[t * DIM + d + 0], W1[(d + 0) * DIM + o], a0);
                a1 = fmaf(emb[t * DIM + d + 1], W1[(d + 1) * DIM + o], a1);
                a2 = fmaf(emb[t * DIM + d + 2], W1[(d + 2) * DIM + o], a2);
                a3 = fmaf(emb[t * DIM + d + 3], W1[(d + 3) * DIM + o], a3);
            }
            g_htab[idx] = (a0 + a1) + (a2 + a3);
        }
        return;
    }
    int e4 = ((b - HTB) * 256 + threadIdx.x) * 4;
    const int* dsts = ei + E;
    if (((E & 3) == 0) && (e4 + 3 < E)) {
        int4 dd = *(const int4*)&dsts[e4];
        atomicAdd(&g_cnt[dd.x], 1);
        atomicAdd(&g_cnt[dd.y], 1);
        atomicAdd(&g_cnt[dd.z], 1);
        atomicAdd(&g_cnt[dd.w], 1);
    } else {
        #pragma unroll
        for (int k = 0; k < 4; k++)
            if (e4 + k < E) atomicAdd(&g_cnt[dsts[e4 + k]], 1);
    }
}

// per-block scan of counts (warp-shuffle); ndp pack; elected last block scans bsums
__global__ void k_scan1(const int* __restrict__ node_ids, int n) {
    __shared__ int wsum[32];
    __shared__ int s2[NBMAX];
    __shared__ int s_elect;
    int t = threadIdx.x;
    int lane = t & 31, w = t >> 5;
    int i = blockIdx.x * 1024 + t;
    int v = (i < n) ? g_cnt[i] : 0;
    if (i < n) {
        float dv = rsqrtf((float)(v + 1));
        g_ndp[i] = (__float_as_uint(dv) & ~31u) | (unsigned)node_ids[i];
    }

    int x = v;
    #pragma unroll
    for (int off = 1; off < 32; off <<= 1) {
        int y = __shfl_up_sync(0xffffffffu, x, off);
        if (lane >= off) x += y;
    }
    if (lane == 31) wsum[w] = x;
    __syncthreads();
    if (w == 0) {
        int y = wsum[lane];
        #pragma unroll
        for (int off = 1; off < 32; off <<= 1) {
            int z = __shfl_up_sync(0xffffffffu, y, off);
            if (lane >= off) y += z;
        }
        wsum[lane] = y;
    }
    __syncthreads();
    int incl = x + (w > 0 ? wsum[w - 1] : 0);
    if (i < n) g_rowptr[i] = incl - v;           // local exclusive
    if (t == 1023) g_bsums[blockIdx.x] = incl;   // block total
    __syncthreads();

    if (t == 0) {
        __threadfence();
        int old = atomicAdd(&g_sctr, 1);
        s_elect = (old == (int)gridDim.x - 1);
    }
    __syncthreads();
    if (s_elect) {
        int nb = gridDim.x;
        int v0 = 0;
        if (t < NBMAX) { v0 = (t < nb) ? g_bsums[t] : 0; s2[t] = v0; }
        __syncthreads();
        #pragma unroll
        for (int off = 1; off < NBMAX; off <<= 1) {
            int a = 0;
            if (t < NBMAX && t >= off) a = s2[t - off];
            __syncthreads();
            if (t < NBMAX) s2[t] += a;
            __syncthreads();
        }
        if (t < nb) g_bsums[t] = s2[t] - v0;     // exclusive block offsets
        if (t == 0) g_sctr = 0;                  // self-reset for next replay
    }
}

// CSR placement, 2 edges/thread; g_cnt doubles as cursor (drains to 0)
__global__ void k_scatter(const int* __restrict__ ei, int E) {
    int e2 = (blockIdx.x * blockDim.x + threadIdx.x) * 2;
    if (((E & 1) == 0) && (e2 + 1 < E)) {
        int2 ss = *(const int2*)&ei[e2];
        int2 dd = *(const int2*)&ei[E + e2];
        int p0 = atomicAdd(&g_cnt[dd.x], -1) - 1;
        int p1 = atomicAdd(&g_cnt[dd.y], -1) - 1;
        unsigned k0 = __ldg(&g_ndp[ss.x]);
        unsigned k1 = __ldg(&g_ndp[ss.y]);
        g_edge[g_rowptr[dd.x] + g_bsums[dd.x >> 10] + p0] = make_int2(ss.x, (int)k0);
        g_edge[g_rowptr[dd.y] + g_bsums[dd.y >> 10] + p1] = make_int2(ss.y, (int)k1);
    } else {
        #pragma unroll
        for (int k = 0; k < 2; k++) {
            int e = e2 + k;
            if (e >= E) break;
            int s = ei[e];
            int d = ei[E + e];
            int p = atomicAdd(&g_cnt[d], -1) - 1;
            g_edge[g_rowptr[d] + g_bsums[d >> 10] + p] = make_int2(s, (int)__ldg(&g_ndp[s]));
        }
    }
}

// Layer 1: 8 nodes/warp, 4 lanes/node, pipelined edge gathers, smem fp32
// coefficient atomics, then HFMA2 accumulate (halved FMA work + registers)
__global__ void __launch_bounds__(256) k_layer1(const float* __restrict__ b1, int n, int E) {
    __shared__ uint2 sh2[NTYPES * 32];    // htab as 2x half2 per lane (4 features)
    __shared__ uint2 sb2[32];             // b1  as 2x half2 per lane
    __shared__ float warpc[8][8][33];     // fp32 coeffs; converted in-place to half2 bits
    for (int i = threadIdx.x; i < NTYPES * 32; i += blockDim.x) {
        float4 hv = ((const float4*)g_htab)[i];
        __half2 h0 = __floats2half2_rn(hv.x, hv.y);
        __half2 h1 = __floats2half2_rn(hv.z, hv.w);
        uint2 u; u.x = *(unsigned*)&h0; u.y = *(unsigned*)&h1;
        sh2[i] = u;
    }
    if (threadIdx.x < 32) {
        float4 bv = ((const float4*)b1)[threadIdx.x];
        __half2 h0 = __floats2half2_rn(bv.x, bv.y);
        __half2 h1 = __floats2half2_rn(bv.z, bv.w);
        uint2 u; u.x = *(unsigned*)&h0; u.y = *(unsigned*)&h1;
        sb2[threadIdx.x] = u;
    }
    __syncthreads();

    int warp = threadIdx.x >> 5, lane = threadIdx.x & 31;
    int ibase = (blockIdx.x * 8 + warp) * 8;
    if (ibase >= n) return;

    #pragma unroll
    for (int j = 0; j < 8; j++) warpc[warp][j][lane] = 0.f;

    int grp = lane >> 2;      // node within warp (0..7)
    int sub = lane & 3;

    // row boundaries: lanes 0..8 fetch, broadcast via shfl
    int rv = E;
    {
        int iq = ibase + lane;
        if (lane < 9 && iq < n) rv = g_rowptr[iq] + g_bsums[iq >> 10];
    }
    int ge0 = __shfl_sync(0xffffffffu, rv, grp);
    int ge1 = __shfl_sync(0xffffffffu, rv, grp + 1);

    // self-loop pre-fold (lanes 0..7 own node j=lane)
    __syncwarp();
    unsigned mypk = 0;
    if (lane < 8 && ibase + lane < n) {
        mypk = g_ndp[ibase + lane];
        warpc[warp][lane][mypk & 31u] += __uint_as_float(mypk & ~31u);
    }
    __syncwarp();

    // pipelined edge loop: 4 lanes per node, one LDG in flight ahead
    if (ibase + grp < n) {
        int e = ge0 + sub;
        if (e < ge1) {
            unsigned pk = (unsigned)__ldg(&g_edge[e].y);
            for (;;) {
                int en = e + 4;
                unsigned pkn = 0;
                bool more = en < ge1;
                if (more) pkn = (unsigned)__ldg(&g_edge[en].y);
                atomicAdd(&warpc[warp][grp][pk & 31u], __uint_as_float(pk & ~31u));
                if (!more) break;
                pk = pkn;
                e = en;
            }
        }
    }
    __syncwarp();

    // convert coefficients in-place: float -> broadcast half2 bits
    #pragma unroll
    for (int k = 0; k < 5; k++) {          // 5*32 >= 8*17
        int idx = k * 32 + lane;
        if (idx < 8 * NTYPES) {
            int j = idx / NTYPES, t = idx - j * NTYPES;
            float c = warpc[warp][j][t];
            __half2 hc = __float2half2_rn(c);
            *(unsigned*)&warpc[warp][j][t] = *(unsigned*)&hc;
        }
    }
    __syncwarp();

    // HFMA2 accumulation: one LDS.64 of h serves 8 nodes
    __half2 acc[8][2];
    #pragma unroll
    for (int j = 0; j < 8; j++) {
        acc[j][0] = __float2half2_rn(0.f);
        acc[j][1] = __float2half2_rn(0.f);
    }
    const unsigned* wcrow = (const unsigned*)&warpc[warp][0][0];
    #pragma unroll
    for (int t = 0; t < NTYPES; t++) {
        uint2 hu = sh2[t * 32 + lane];
        __half2 h0 = *(__half2*)&hu.x;
        __half2 h1 = *(__half2*)&hu.y;
        #pragma unroll
        for (int j = 0; j < 8; j++) {
            unsigned cu = wcrow[j * 33 + t];
            __half2 hc = *(__half2*)&cu;
            acc[j][0] = __hfma2(hc, h0, acc[j][0]);
            acc[j][1] = __hfma2(hc, h1, acc[j][1]);
        }
    }

    uint2 bu = sb2[lane];
    __half2 bb0 = *(__half2*)&bu.x;
    __half2 bb1 = *(__half2*)&bu.y;
    __half2 zero = __float2half2_rn(0.f);
    #pragma unroll
    for (int j = 0; j < 8; j++) {
        int i = ibase + j;
        if (i >= n) break;
        float dij = __shfl_sync(0xffffffffu, __uint_as_float(mypk & ~31u), j);
        __half2 d2 = __float2half2_rn(dij);
        __half2 r0 = __hmul2(d2, __hmax2(__hfma2(d2, acc[j][0], bb0), zero));
        __half2 r1 = __hmul2(d2, __hmax2(__hfma2(d2, acc[j][1], bb1), zero));
        uint2 u;
        u.x = *(unsigned*)&r0;
        u.y = *(unsigned*)&r1;
        g_y1h[(size_t)i * 32 + lane] = u;
    }
}

__device__ __forceinline__ void acc_row(float4& acc, uint2 u) {
    float2 f0 = __half22float2(*(__half2*)&u.x);
    float2 f1 = __half22float2(*(__half2*)&u.y);
    acc.x += f0.x; acc.y += f0.y; acc.z += f1.x; acc.w += f1.y;
}

// Layer 2 aggregation (fp16 gather, fp32 accum) fused with graph pooling
__global__ void __launch_bounds__(256) k_layer2pool(const int* __restrict__ batch, int n, int E) {
    __shared__ float sy[8 * DIM];
    __shared__ int sg[8];

    int warp = threadIdx.x >> 5, lane = threadIdx.x & 31;
    int i = blockIdx.x * 8 + warp;

    if (i < n) {
        const uint2* y = (const uint2*)g_y1h;
        float di = __uint_as_float(g_ndp[i] & ~31u);
        float4 acc = {0.f, 0.f, 0.f, 0.f};
        acc_row(acc, __ldg(&y[(size_t)i * 32 + lane]));   // self loop

        int e  = g_rowptr[i] + g_bsums[i >> 10];
        int e1 = (i + 1 < n) ? (g_rowptr[i + 1] + g_bsums[(i + 1) >> 10]) : E;

        for (; e + 8 <= e1; e += 8) {
            int s0 = g_edge[e + 0].x, s1 = g_edge[e + 1].x;
            int s2 = g_edge[e + 2].x, s3 = g_edge[e + 3].x;
            int s4 = g_edge[e + 4].x, s5 = g_edge[e + 5].x;
            int s6 = g_edge[e + 6].x, s7 = g_edge[e + 7].x;
            uint2 u0 = __ldg(&y[(size_t)s0 * 32 + lane]);
            uint2 u1 = __ldg(&y[(size_t)s1 * 32 + lane]);
            uint2 u2 = __ldg(&y[(size_t)s2 * 32 + lane]);
            uint2 u3 = __ldg(&y[(size_t)s3 * 32 + lane]);
            uint2 u4 = __ldg(&y[(size_t)s4 * 32 + lane]);
            uint2 u5 = __ldg(&y[(size_t)s5 * 32 + lane]);
            uint2 u6 = __ldg(&y[(size_t)s6 * 32 + lane]);
            uint2 u7 = __ldg(&y[(size_t)s7 * 32 + lane]);
            acc_row(acc, u0); acc_row(acc, u1); acc_row(acc, u2); acc_row(acc, u3);
            acc_row(acc, u4); acc_row(acc, u5); acc_row(acc, u6); acc_row(acc, u7);
        }
        if (e + 4 <= e1) {
            int s0 = g_edge[e + 0].x, s1 = g_edge[e + 1].x;
            int s2 = g_edge[e + 2].x, s3 = g_edge[e + 3].x;
            uint2 u0 = __ldg(&y[(size_t)s0 * 32 + lane]);
            uint2 u1 = __ldg(&y[(size_t)s1 * 32 + lane]);
            uint2 u2 = __ldg(&y[(size_t)s2 * 32 + lane]);
            uint2 u3 = __ldg(&y[(size_t)s3 * 32 + lane]);
            acc_row(acc, u0); acc_row(acc, u1); acc_row(acc, u2); acc_row(acc, u3);
            e += 4;
        }
        for (; e < e1; e++)
            acc_row(acc, __ldg(&y[(size_t)g_edge[e].x * 32 + lane]));

        acc.x *= di; acc.y *= di; acc.z *= di; acc.w *= di;
        ((float4*)sy)[warp * 32 + lane] = acc;
        if (lane == 0) sg[warp] = batch[i];
    } else {
        if (lane == 0) sg[warp] = -1;
    }
    __syncthreads();

    int f = threadIdx.x;
    if (f < DIM) {
        float run = 0.f; int cg = -1; int cnt = 0;
        #pragma unroll
        for (int r = 0; r < 8; r++) {
            int g = sg[r];
            if (g < 0) continue;
            if (g != cg) {
                if (cg >= 0) {
                    atomicAdd(&g_pool[cg * DIM + f], run);
                    if (f == 0) atomicAdd(&g_gcnt[cg], cnt);
                }
                cg = g; run = 0.f; cnt = 0;
            }
            run += sy[r * DIM + f];
            cnt++;
        }
        if (cg >= 0) {
            atomicAdd(&g_pool[cg * DIM + f], run);
            if (f == 0) atomicAdd(&g_gcnt[cg], cnt);
        }
    }
}

// out[g] = (pool[g]/cnt[g]) @ W2 + b2 ; re-zeros pool/gcnt for next replay
__global__ void k_final(const float* __restrict__ W2, const float* __restrict__ b2,
                        float* __restrict__ out) {
    int g = blockIdx.x, o = threadIdx.x;
    __shared__ float p[DIM];
    int c = g_gcnt[g];
    float inv = (c > 0) ? (1.0f / (float)c) : 0.f;
    p[o] = g_pool[g * DIM + o] * inv;
    g_pool[g * DIM + o] = 0.f;
    if (o == 0) g_gcnt[g] = 0;
    __syncthreads();
    float a0 = 0.f, a1 = 0.f, a2 = 0.f, a3 = 0.f;
    #pragma unroll
    for (int d = 0; d < DIM; d += 4) {
        a0 = fmaf(p[d + 0], W2[(d + 0) * DIM + o], a0);
        a1 = fmaf(p[d + 1], W2[(d + 1) * DIM + o], a1);
        a2 = fmaf(p[d + 2], W2[(d + 2) * DIM + o], a2);
        a3 = fmaf(p[d + 3], W2[(d + 3) * DIM + o], a3);
    }
    out[g * DIM + o] = (c > 0) ? ((a0 + a1) + (a2 + a3) + b2[o]) : 0.f;
}

// ---------------- launcher ----------------
extern "C" void kernel_launch(void* const* d_in, const int* in_sizes, int n_in,
                              void* d_out, int out_size) {
    const int* node_ids = (const int*)d_in[0];
    const int* ei       = (const int*)d_in[1];
    const int* batch    = (const int*)d_in[2];
    int base = (n_in >= 9 && in_sizes[3] == 1) ? 4 : 3;
    const float* emb = (const float*)d_in[base + 0];
    const float* W1  = (const float*)d_in[base + 1];
    const float* b1  = (const float*)d_in[base + 2];
    const float* W2  = (const float*)d_in[base + 3];
    const float* b2  = (const float*)d_in[base + 4];

    int N = in_sizes[0];
    int E = in_sizes[1] / 2;
    int G = out_size / DIM;
    int NB = (N + 1023) / 1024;
    int Equads = (E + 3) / 4;
    int Epairs = (E + 1) / 2;

    k_hist<<<HTB + (Equads + 255) / 256, 256>>>(ei, E, emb, W1);
    k_scan1<<<NB, 1024>>>(node_ids, N);
    k_scatter<<<(Epairs + 255) / 256, 256>>>(ei, E);
    k_layer1<<<(N + 63) / 64, 256>>>(b1, N, E);
    k_layer2pool<<<(N + 7) / 8, 256>>>(batch, N, E);
    k_final<<<G, DIM>>>(W2, b2, (float*)d_out);
}

// round 14
// speedup vs baseline: 1.0071x; 1.0071x over previous
#include <cuda_runtime.h>
#include <cuda_fp16.h>
#include <math.h>

#define NMAX    100000
#define EMAX    1600000
#define NTYPES  17
#define DIM     128
#define GMAX    64
#define NBMAX   128
#define HTB     9      // htab helper blocks inside k_hist

// ---------------- static scratch (all zero-init; self-restoring across replays) ----------------
__device__ int   g_cnt[NMAX];      // hist fills; scatter drains back to 0
__device__ int   g_rowptr[NMAX];   // local-exclusive; + g_bsums[i>>10] on use
__device__ int   g_bsums[NBMAX];
__device__ int   g_sctr;           // scan election counter (self-resets)
__device__ unsigned g_ndp[NMAX];   // (dinv bits & ~31) | type
__device__ int2  g_edge[EMAX];     // {src, (dinv_src bits & ~31) | type_src}
__device__ float g_htab[NTYPES * DIM];
__device__ unsigned g_y1b[(size_t)NMAX * 32]; // fp8 e4m3 x4 per lane: y1s = dinv*relu(conv1)
__device__ float g_pool[GMAX * DIM];          // k_final re-zeros
__device__ int   g_gcnt[GMAX];                // k_final re-zeros

// ---------------- fp8 helpers ----------------
__device__ __forceinline__ unsigned pack_f4_e4m3(float x, float y, float z, float w) {
    unsigned short p01, p23;
    asm("cvt.rn.satfinite.e4m3x2.f32 %0, %1, %2;" : "=h"(p01) : "f"(y), "f"(x));
    asm("cvt.rn.satfinite.e4m3x2.f32 %0, %1, %2;" : "=h"(p23) : "f"(w), "f"(z));
    return ((unsigned)p23 << 16) | (unsigned)p01;
}

__device__ __forceinline__ void h2acc(unsigned u, __half2& a0, __half2& a1) {
    unsigned short lo = (unsigned short)(u & 0xffffu);
    unsigned short hi = (unsigned short)(u >> 16);
    unsigned c0, c1;
    asm("cvt.rn.f16x2.e4m3x2 %0, %1;" : "=r"(c0) : "h"(lo));
    asm("cvt.rn.f16x2.e4m3x2 %0, %1;" : "=r"(c1) : "h"(hi));
    a0 = __hadd2(a0, *(__half2*)&c0);
    a1 = __hadd2(a1, *(__half2*)&c1);
}

__device__ __forceinline__ void flushacc(float4& acc, __half2& h0, __half2& h1) {
    float2 f0 = __half22float2(h0);
    float2 f1 = __half22float2(h1);
    acc.x += f0.x; acc.y += f0.y; acc.z += f1.x; acc.w += f1.y;
    h0 = __float2half2_rn(0.f);
    h1 = __float2half2_rn(0.f);
}

// ---------------- kernels ----------------

// blocks 0..HTB-1: htab = emb @ W1 ; rest: in-degree histogram (2 edges/thread)
__global__ void __launch_bounds__(256) k_hist(const int* __restrict__ ei, int E,
                                              const float* __restrict__ emb,
                                              const float* __restrict__ W1) {
    int b = blockIdx.x;
    if (b < HTB) {
        int idx = b * 256 + threadIdx.x;
        if (idx < NTYPES * DIM) {
            int t = idx / DIM, o = idx % DIM;
            float a0 = 0.f, a1 = 0.f, a2 = 0.f, a3 = 0.f;
            #pragma unroll
            for (int d = 0; d < DIM; d += 4) {
                a0 = fmaf(emb[t * DIM + d + 0], W1[(d + 0) * DIM + o], a0);
                a1 = fmaf(emb[t * DIM + d + 1], W1[(d + 1) * DIM + o], a1);
                a2 = fmaf(emb[t * DIM + d + 2], W1[(d + 2) * DIM + o], a2);
                a3 = fmaf(emb[t * DIM + d + 3], W1[(d + 3) * DIM + o], a3);
            }
            g_htab[idx] = (a0 + a1) + (a2 + a3);
        }
        return;
    }
    int e2 = ((b - HTB) * 256 + threadIdx.x) * 2;
    if (e2 + 1 < E) {
        int2 dd = *(const int2*)&ei[E + e2];
        atomicAdd(&g_cnt[dd.x], 1);
        atomicAdd(&g_cnt[dd.y], 1);
    } else if (e2 < E) {
        atomicAdd(&g_cnt[ei[E + e2]], 1);
    }
}

// per-block scan of counts (warp-shuffle); ndp pack; elected last block scans bsums
__global__ void k_scan1(const int* __restrict__ node_ids, int n) {
    __shared__ int wsum[32];
    __shared__ int s2[NBMAX];
    __shared__ int s_elect;
    int t = threadIdx.x;
    int lane = t & 31, w = t >> 5;
    int i = blockIdx.x * 1024 + t;
    int v = (i < n) ? g_cnt[i] : 0;
    if (i < n) {
        float dv = rsqrtf((float)(v + 1));
        g_ndp[i] = (__float_as_uint(dv) & ~31u) | (unsigned)node_ids[i];
    }

    int x = v;
    #pragma unroll
    for (int off = 1; off < 32; off <<= 1) {
        int y = __shfl_up_sync(0xffffffffu, x, off);
        if (lane >= off) x += y;
    }
    if (lane == 31) wsum[w] = x;
    __syncthreads();
    if (w == 0) {
        int y = wsum[lane];
        #pragma unroll
        for (int off = 1; off < 32; off <<= 1) {
            int z = __shfl_up_sync(0xffffffffu, y, off);
            if (lane >= off) y += z;
        }
        wsum[lane] = y;
    }
    __syncthreads();
    int incl = x + (w > 0 ? wsum[w - 1] : 0);
    if (i < n) g_rowptr[i] = incl - v;           // local exclusive
    if (t == 1023) g_bsums[blockIdx.x] = incl;   // block total
    __syncthreads();

    if (t == 0) {
        __threadfence();
        int old = atomicAdd(&g_sctr, 1);
        s_elect = (old == (int)gridDim.x - 1);
    }
    __syncthreads();
    if (s_elect) {
        int nb = gridDim.x;
        int v0 = 0;
        if (t < NBMAX) { v0 = (t < nb) ? g_bsums[t] : 0; s2[t] = v0; }
        __syncthreads();
        #pragma unroll
        for (int off = 1; off < NBMAX; off <<= 1) {
            int a = 0;
            if (t < NBMAX && t >= off) a = s2[t - off];
            __syncthreads();
            if (t < NBMAX) s2[t] += a;
            __syncthreads();
        }
        if (t < nb) g_bsums[t] = s2[t] - v0;     // exclusive block offsets
        if (t == 0) g_sctr = 0;                  // self-reset for next replay
    }
}

// CSR placement; g_cnt doubles as cursor (drains to 0)
__global__ void k_scatter(const int* __restrict__ ei, int E) {
    int e = blockIdx.x * blockDim.x + threadIdx.x;
    if (e >= E) return;
    int s = ei[e];
    int d = ei[E + e];
    int p = atomicAdd(&g_cnt[d], -1) - 1;
    g_edge[g_rowptr[d] + g_bsums[d >> 10] + p] = make_int2(s, (int)__ldg(&g_ndp[s]));
}

// Layer 1: 8 nodes/warp, 4 lanes/node, pipelined edge gathers, smem fp32
// coefficient atomics, then HFMA2 accumulate; OUTPUT fp8 e4m3 (4B/lane)
__global__ void __launch_bounds__(256) k_layer1(const float* __restrict__ b1, int n, int E) {
    __shared__ uint2 sh2[NTYPES * 32];    // htab as 2x half2 per lane (4 features)
    __shared__ uint2 sb2[32];             // b1  as 2x half2 per lane
    __shared__ float warpc[8][8][33];     // fp32 coeffs; converted in-place to half2 bits
    for (int i = threadIdx.x; i < NTYPES * 32; i += blockDim.x) {
        float4 hv = ((const float4*)g_htab)[i];
        __half2 h0 = __floats2half2_rn(hv.x, hv.y);
        __half2 h1 = __floats2half2_rn(hv.z, hv.w);
        uint2 u; u.x = *(unsigned*)&h0; u.y = *(unsigned*)&h1;
        sh2[i] = u;
    }
    if (threadIdx.x < 32) {
        float4 bv = ((const float4*)b1)[threadIdx.x];
        __half2 h0 = __floats2half2_rn(bv.x, bv.y);
        __half2 h1 = __floats2half2_rn(bv.z, bv.w);
        uint2 u; u.x = *(unsigned*)&h0; u.y = *(unsigned*)&h1;
        sb2[threadIdx.x] = u;
    }
    __syncthreads();

    int warp = threadIdx.x >> 5, lane = threadIdx.x & 31;
    int ibase = (blockIdx.x * 8 + warp) * 8;
    if (ibase >= n) return;

    #pragma unroll
    for (int j = 0; j < 8; j++) warpc[warp][j][lane] = 0.f;

    int grp = lane >> 2;      // node within warp (0..7)
    int sub = lane & 3;

    // row boundaries: lanes 0..8 fetch, broadcast via shfl
    int rv = E;
    {
        int iq = ibase + lane;
        if (lane < 9 && iq < n) rv = g_rowptr[iq] + g_bsums[iq >> 10];
    }
    int ge0 = __shfl_sync(0xffffffffu, rv, grp);
    int ge1 = __shfl_sync(0xffffffffu, rv, grp + 1);

    // self-loop pre-fold (lanes 0..7 own node j=lane)
    __syncwarp();
    unsigned mypk = 0;
    if (lane < 8 && ibase + lane < n) {
        mypk = g_ndp[ibase + lane];
        warpc[warp][lane][mypk & 31u] += __uint_as_float(mypk & ~31u);
    }
    __syncwarp();

    // pipelined edge loop: 4 lanes per node, one LDG in flight ahead
    if (ibase + grp < n) {
        int e = ge0 + sub;
        if (e < ge1) {
            unsigned pk = (unsigned)__ldg(&g_edge[e].y);
            for (;;) {
                int en = e + 4;
                unsigned pkn = 0;
                bool more = en < ge1;
                if (more) pkn = (unsigned)__ldg(&g_edge[en].y);
                atomicAdd(&warpc[warp][grp][pk & 31u], __uint_as_float(pk & ~31u));
                if (!more) break;
                pk = pkn;
                e = en;
            }
        }
    }
    __syncwarp();

    // convert coefficients in-place: float -> broadcast half2 bits
    #pragma unroll
    for (int k = 0; k < 5; k++) {          // 5*32 >= 8*17
        int idx = k * 32 + lane;
        if (idx < 8 * NTYPES) {
            int j = idx / NTYPES, t = idx - j * NTYPES;
            float c = warpc[warp][j][t];
            __half2 hc = __float2half2_rn(c);
            *(unsigned*)&warpc[warp][j][t] = *(unsigned*)&hc;
        }
    }
    __syncwarp();

    // HFMA2 accumulation: one LDS.64 of h serves 8 nodes
    __half2 acc[8][2];
    #pragma unroll
    for (int j = 0; j < 8; j++) {
        acc[j][0] = __float2half2_rn(0.f);
        acc[j][1] = __float2half2_rn(0.f);
    }
    const unsigned* wcrow = (const unsigned*)&warpc[warp][0][0];
    #pragma unroll
    for (int t = 0; t < NTYPES; t++) {
        uint2 hu = sh2[t * 32 + lane];
        __half2 h0 = *(__half2*)&hu.x;
        __half2 h1 = *(__half2*)&hu.y;
        #pragma unroll
        for (int j = 0; j < 8; j++) {
            unsigned cu = wcrow[j * 33 + t];
            __half2 hc = *(__half2*)&cu;
            acc[j][0] = __hfma2(hc, h0, acc[j][0]);
            acc[j][1] = __hfma2(hc, h1, acc[j][1]);
        }
    }

    uint2 bu = sb2[lane];
    __half2 bb0 = *(__half2*)&bu.x;
    __half2 bb1 = *(__half2*)&bu.y;
    __half2 zero = __float2half2_rn(0.f);
    #pragma unroll
    for (int j = 0; j < 8; j++) {
        int i = ibase + j;
        if (i >= n) break;
        float dij = __shfl_sync(0xffffffffu, __uint_as_float(mypk & ~31u), j);
        __half2 d2 = __float2half2_rn(dij);
        __half2 r0 = __hmul2(d2, __hmax2(__hfma2(d2, acc[j][0], bb0), zero));
        __half2 r1 = __hmul2(d2, __hmax2(__hfma2(d2, acc[j][1], bb1), zero));
        float2 f0 = __half22float2(r0);
        float2 f1 = __half22float2(r1);
        g_y1b[(size_t)i * 32 + lane] = pack_f4_e4m3(f0.x, f0.y, f1.x, f1.y);
    }
}

// Layer 2 aggregation (fp8 gather, fp16 accumulate + fp32 flush every 8) + pooling
__global__ void __launch_bounds__(256) k_layer2pool(const int* __restrict__ batch, int n, int E) {
    __shared__ float sy[8 * DIM];
    __shared__ int sg[8];

    int warp = threadIdx.x >> 5, lane = threadIdx.x & 31;
    int i = blockIdx.x * 8 + warp;

    if (i < n) {
        const unsigned* y = (const unsigned*)g_y1b;
        float di = __uint_as_float(g_ndp[i] & ~31u);
        float4 acc = {0.f, 0.f, 0.f, 0.f};
        __half2 h0 = __float2half2_rn(0.f), h1 = __float2half2_rn(0.f);

        h2acc(__ldg(&y[(size_t)i * 32 + lane]), h0, h1);   // self loop

        int e  = g_rowptr[i] + g_bsums[i >> 10];
        int e1 = (i + 1 < n) ? (g_rowptr[i + 1] + g_bsums[(i + 1) >> 10]) : E;

        for (; e + 8 <= e1; e += 8) {
            int s0 = g_edge[e + 0].x, s1 = g_edge[e + 1].x;
            int s2 = g_edge[e + 2].x, s3 = g_edge[e + 3].x;
            int s4 = g_edge[e + 4].x, s5 = g_edge[e + 5].x;
            int s6 = g_edge[e + 6].x, s7 = g_edge[e + 7].x;
            unsigned u0 = __ldg(&y[(size_t)s0 * 32 + lane]);
            unsigned u1 = __ldg(&y[(size_t)s1 * 32 + lane]);
            unsigned u2 = __ldg(&y[(size_t)s2 * 32 + lane]);
            unsigned u3 = __ldg(&y[(size_t)s3 * 32 + lane]);
            unsigned u4 = __ldg(&y[(size_t)s4 * 32 + lane]);
            unsigned u5 = __ldg(&y[(size_t)s5 * 32 + lane]);
            unsigned u6 = __ldg(&y[(size_t)s6 * 32 + lane]);
            unsigned u7 = __ldg(&y[(size_t)s7 * 32 + lane]);
            h2acc(u0, h0, h1); h2acc(u1, h0, h1); h2acc(u2, h0, h1); h2acc(u3, h0, h1);
            h2acc(u4, h0, h1); h2acc(u5, h0, h1); h2acc(u6, h0, h1); h2acc(u7, h0, h1);
            flushacc(acc, h0, h1);
        }
        for (; e < e1; e++)
            h2acc(__ldg(&y[(size_t)g_edge[e].x * 32 + lane]), h0, h1);
        flushacc(acc, h0, h1);

        acc.x *= di; acc.y *= di; acc.z *= di; acc.w *= di;
        ((float4*)sy)[warp * 32 + lane] = acc;
        if (lane == 0) sg[warp] = batch[i];
    } else {
        if (lane == 0) sg[warp] = -1;
    }
    __syncthreads();

    int f = threadIdx.x;
    if (f < DIM) {
        float run = 0.f; int cg = -1; int cnt = 0;
        #pragma unroll
        for (int r = 0; r < 8; r++) {
            int g = sg[r];
            if (g < 0) continue;
            if (g != cg) {
                if (cg >= 0) {
                    atomicAdd(&g_pool[cg * DIM + f], run);
                    if (f == 0) atomicAdd(&g_gcnt[cg], cnt);
                }
                cg = g; run = 0.f; cnt = 0;
            }
            run += sy[r * DIM + f];
            cnt++;
        }
        if (cg >= 0) {
            atomicAdd(&g_pool[cg * DIM + f], run);
            if (f == 0) atomicAdd(&g_gcnt[cg], cnt);
        }
    }
}

// out[g] = (pool[g]/cnt[g]) @ W2 + b2 ; re-zeros pool/gcnt for next replay
__global__ void k_final(const float* __restrict__ W2, const float* __restrict__ b2,
                        float* __restrict__ out) {
    int g = blockIdx.x, o = threadIdx.x;
    __shared__ float p[DIM];
    int c = g_gcnt[g];
    float inv = (c > 0) ? (1.0f / (float)c) : 0.f;
    p[o] = g_pool[g * DIM + o] * inv;
    g_pool[g * DIM + o] = 0.f;
    if (o == 0) g_gcnt[g] = 0;
    __syncthreads();
    float a0 = 0.f, a1 = 0.f, a2 = 0.f, a3 = 0.f;
    #pragma unroll
    for (int d = 0; d < DIM; d += 4) {
        a0 = fmaf(p[d + 0], W2[(d + 0) * DIM + o], a0);
        a1 = fmaf(p[d + 1], W2[(d + 1) * DIM + o], a1);
        a2 = fmaf(p[d + 2], W2[(d + 2) * DIM + o], a2);
        a3 = fmaf(p[d + 3], W2[(d + 3) * DIM + o], a3);
    }
    out[g * DIM + o] = (c > 0) ? ((a0 + a1) + (a2 + a3) + b2[o]) : 0.f;
}

// ---------------- launcher ----------------
extern "C" void kernel_launch(void* const* d_in, const int* in_sizes, int n_in,
                              void* d_out, int out_size) {
    const int* node_ids = (const int*)d_in[0];
    const int* ei       = (const int*)d_in[1];
    const int* batch    = (const int*)d_in[2];
    int base = (n_in >= 9 && in_sizes[3] == 1) ? 4 : 3;
    const float* emb = (const float*)d_in[base + 0];
    const float* W1  = (const float*)d_in[base + 1];
    const float* b1  = (const float*)d_in[base + 2];
    const float* W2  = (const float*)d_in[base + 3];
    const float* b2  = (const float*)d_in[base + 4];

    int N = in_sizes[0];
    int E = in_sizes[1] / 2;
    int G = out_size / DIM;
    int NB = (N + 1023) / 1024;
    int Epairs = (E + 1) / 2;

    k_hist<<<HTB + (Epairs + 255) / 256, 256>>>(ei, E, emb, W1);
    k_scan1<<<NB, 1024>>>(node_ids, N);
    k_scatter<<<(E + 255) / 256, 256>>>(ei, E);
    k_layer1<<<(N + 63) / 64, 256>>>(b1, N, E);
    k_layer2pool<<<(N + 7) / 8, 256>>>(batch, N, E);
    k_final<<<G, DIM>>>(W2, b2, (float*)d_out);
}